// round 14
// baseline (speedup 1.0000x reference)
#include <cuda_runtime.h>
#include <cuda_bf16.h>
#include <cstdint>

#define S_LEN 2048
#define DM    4096
#define NH    32
#define HD    128
#define WIN   1024

// ---------------- scratch (__device__ globals; no allocation APIs) ----------
__device__ __nv_bfloat16 d_xh[S_LEN * DM], d_xl[S_LEN * DM];   // x split
__device__ __nv_bfloat16 d_ah[S_LEN * DM], d_al[S_LEN * DM];   // attn-out split
__device__ __nv_bfloat16 d_wh[4][DM * DM], d_wl[4][DM * DM];   // Wq,Wk,Wv,Wo

// attention operands (bf16 hi/lo)
__device__ __nv_bfloat16 d_qh[S_LEN * DM], d_ql[S_LEN * DM];   // Q (pre-scaled)
__device__ __nv_bfloat16 d_kh2[S_LEN * DM], d_kl2[S_LEN * DM]; // K
__device__ __nv_bfloat16 d_vth[S_LEN * DM], d_vtl[S_LEN * DM]; // V^T [h*128+d][s]

// ---------------- PTX helpers (sm_80-class only) ----------------------------
__device__ __forceinline__ uint32_t s2u(const void* p) {
    uint32_t r;
    asm("{ .reg .u64 t; cvta.to.shared.u64 t, %1; cvt.u32.u64 %0, t; }"
        : "=r"(r) : "l"(p));
    return r;
}
#define LDSM4(r0, r1, r2, r3, addr) \
    asm volatile("ldmatrix.sync.aligned.m8n8.x4.shared.b16 {%0,%1,%2,%3}, [%4];" \
        : "=r"(r0), "=r"(r1), "=r"(r2), "=r"(r3) : "r"(addr))
__device__ __forceinline__ void mma16816(float* c, const uint32_t* a, const uint32_t* b) {
    asm volatile(
        "mma.sync.aligned.m16n8k16.row.col.f32.bf16.bf16.f32 "
        "{%0,%1,%2,%3}, {%4,%5,%6,%7}, {%8,%9}, {%0,%1,%2,%3};"
        : "+f"(c[0]), "+f"(c[1]), "+f"(c[2]), "+f"(c[3])
        : "r"(a[0]), "r"(a[1]), "r"(a[2]), "r"(a[3]), "r"(b[0]), "r"(b[1]));
}
#define CPA16(dst, src) \
    asm volatile("cp.async.cg.shared.global [%0], [%1], 16;" :: "r"(dst), "l"(src))
#define CPC()  asm volatile("cp.async.commit_group;")
#define CPW1() asm volatile("cp.async.wait_group 1;")
#define CPW0() asm volatile("cp.async.wait_group 0;")

// 16B-chunk XOR swizzles
__device__ __forceinline__ uint32_t tile_off(int row, int ck) {        // 4 chunks/row
    return (uint32_t)(((row << 2) + (ck ^ ((row >> 1) & 3))) << 4);
}
__device__ __forceinline__ uint32_t swz16(int r, int c) {              // 16 chunks/row
    return (uint32_t)((c & 8) | ((c ^ (r & 7)) & 7));
}
__device__ __forceinline__ uint32_t swz8(int r, int c) {               // 8 chunks/row
    return (uint32_t)(c ^ (r & 7));
}
__device__ __forceinline__ void split2(float x, float y, uint32_t& hi, uint32_t& lo) {
    __nv_bfloat16 hx = __float2bfloat16(x), hy = __float2bfloat16(y);
    __nv_bfloat162 hp = __halves2bfloat162(hx, hy);
    hi = *reinterpret_cast<uint32_t*>(&hp);
    __nv_bfloat16 lx = __float2bfloat16(x - __bfloat162float(hx));
    __nv_bfloat16 ly = __float2bfloat16(y - __bfloat162float(hy));
    __nv_bfloat162 lp = __halves2bfloat162(lx, ly);
    lo = *reinterpret_cast<uint32_t*>(&lp);
}

// ---------------------------------------------------------------------------
// Split fp32 -> bf16 hi/lo
// ---------------------------------------------------------------------------
__device__ __forceinline__ void split_body(const float* __restrict__ s,
                                           __nv_bfloat16* __restrict__ hi,
                                           __nv_bfloat16* __restrict__ lo, int i4)
{
    float4 v = ((const float4*)s)[i4];
    __nv_bfloat16 h0 = __float2bfloat16(v.x);
    __nv_bfloat16 h1 = __float2bfloat16(v.y);
    __nv_bfloat16 h2 = __float2bfloat16(v.z);
    __nv_bfloat16 h3 = __float2bfloat16(v.w);
    __nv_bfloat16 l0 = __float2bfloat16(v.x - __bfloat162float(h0));
    __nv_bfloat16 l1 = __float2bfloat16(v.y - __bfloat162float(h1));
    __nv_bfloat16 l2 = __float2bfloat16(v.z - __bfloat162float(h2));
    __nv_bfloat16 l3 = __float2bfloat16(v.w - __bfloat162float(h3));
    ((__nv_bfloat162*)hi)[i4 * 2 + 0] = __halves2bfloat162(h0, h1);
    ((__nv_bfloat162*)hi)[i4 * 2 + 1] = __halves2bfloat162(h2, h3);
    ((__nv_bfloat162*)lo)[i4 * 2 + 0] = __halves2bfloat162(l0, l1);
    ((__nv_bfloat162*)lo)[i4 * 2 + 1] = __halves2bfloat162(l2, l3);
}

__global__ void split_x_kernel(const float* __restrict__ src)   // x -> d_xh/d_xl
{
    int i4 = blockIdx.x * blockDim.x + threadIdx.x;
    split_body(src, d_xh, d_xl, i4);
}
// all four weights in one launch: grid = 4 * 16384
__global__ void split_w_kernel(const float* __restrict__ Wq, const float* __restrict__ Wk,
                               const float* __restrict__ Wv, const float* __restrict__ Wo)
{
    int w  = blockIdx.x >> 14;
    int i4 = (blockIdx.x & 16383) * blockDim.x + threadIdx.x;
    const float* s = (w == 0) ? Wq : (w == 1) ? Wk : (w == 2) ? Wv : Wo;
    split_body(s, d_wh[w], d_wl[w], i4);
}

// ---------------------------------------------------------------------------
// mma.sync bf16-split GEMM mainloop.  BM=BN=128, BK=32, 256 thr, 3-stage,
// single barrier per kt.  MMA issue reordered: 3 passes of 16 independent
// accumulators (same per-acc product order hh->hl->lh => bit-identical).
// ---------------------------------------------------------------------------
#define GEMM_SMEM (3 * 32768)

__device__ __forceinline__ void gemm_mainloop(
    const __nv_bfloat16* __restrict__ Ah, const __nv_bfloat16* __restrict__ Al,
    const __nv_bfloat16* __restrict__ Bh, const __nv_bfloat16* __restrict__ Bl,
    int bm, int bn, uint32_t sb, float acc[16][4])
{
    const int tid  = threadIdx.x;
    const int lane = tid & 31;
    const int warp = tid >> 5;
    const int wm   = warp & 1;
    const int wn   = warp >> 1;

#pragma unroll
    for (int i = 0; i < 16; i++)
#pragma unroll
        for (int j = 0; j < 4; j++) acc[i][j] = 0.0f;

#define PREFETCH(kt, bi)                                                        \
    do {                                                                        \
        const int k0_ = (kt) * 32;                                              \
        const uint32_t bufb_ = sb + (bi) * 32768;                               \
        _Pragma("unroll")                                                       \
        for (int t_ = 0; t_ < 2; t_++) {                                        \
            int cid_ = tid + t_ * 256;                                          \
            int row_ = cid_ >> 2, ck_ = cid_ & 3;                               \
            uint32_t so_ = tile_off(row_, ck_);                                 \
            size_t ga_ = (size_t)(bm + row_) * DM + k0_ + ck_ * 8;              \
            size_t gb_ = (size_t)(bn + row_) * DM + k0_ + ck_ * 8;              \
            CPA16(bufb_ + so_,          Ah + ga_);                              \
            CPA16(bufb_ + 8192 + so_,   Al + ga_);                              \
            CPA16(bufb_ + 16384 + so_,  Bh + gb_);                              \
            CPA16(bufb_ + 24576 + so_,  Bl + gb_);                              \
        }                                                                       \
    } while (0)

    PREFETCH(0, 0); CPC();
    PREFETCH(1, 1); CPC();

    const int arow = (lane & 15) + wm * 64;
    const int acks = (lane >> 4);
    const int bnrw = wn * 32 + (lane & 7) + ((lane >> 4) << 3);
    const int bcks = ((lane >> 3) & 1);

    int bi = 0, bnext = 2;
    for (int kt = 0; kt < 128; kt++) {
        if (kt < 127) { CPW1(); } else { CPW0(); }
        __syncthreads();
        if (kt + 2 < 128) {
            PREFETCH(kt + 2, bnext);   // safe: buffer consumed by all at kt-1
            CPC();
        }

        const uint32_t bAh = sb + bi * 32768;
        const uint32_t bAl = bAh + 8192;
        const uint32_t bBh = bAh + 16384;
        const uint32_t bBl = bAh + 24576;

#pragma unroll
        for (int s = 0; s < 2; s++) {
            uint32_t ah[4][4], al[4][4], bh[4][2], bl[4][2];
            const int ack = 2 * s + acks;
            const int bck = 2 * s + bcks;
#pragma unroll
            for (int mt = 0; mt < 4; mt++) {
                uint32_t off = tile_off(arow + mt * 16, ack);
                LDSM4(ah[mt][0], ah[mt][1], ah[mt][2], ah[mt][3], bAh + off);
                LDSM4(al[mt][0], al[mt][1], al[mt][2], al[mt][3], bAl + off);
            }
#pragma unroll
            for (int p = 0; p < 2; p++) {
                uint32_t off = tile_off(bnrw + p * 16, bck);
                uint32_t t0, t1, t2, t3;
                LDSM4(t0, t1, t2, t3, bBh + off);
                bh[2 * p][0] = t0; bh[2 * p][1] = t1;
                bh[2 * p + 1][0] = t2; bh[2 * p + 1][1] = t3;
                LDSM4(t0, t1, t2, t3, bBl + off);
                bl[2 * p][0] = t0; bl[2 * p][1] = t1;
                bl[2 * p + 1][0] = t2; bl[2 * p + 1][1] = t3;
            }
            // pass 1: hh (16 independent accs)
#pragma unroll
            for (int mt = 0; mt < 4; mt++)
#pragma unroll
                for (int nt = 0; nt < 4; nt++)
                    mma16816(acc[mt * 4 + nt], ah[mt], bh[nt]);
            // pass 2: hl (distance 16 from pass-1 write)
#pragma unroll
            for (int mt = 0; mt < 4; mt++)
#pragma unroll
                for (int nt = 0; nt < 4; nt++)
                    mma16816(acc[mt * 4 + nt], ah[mt], bl[nt]);
            // pass 3: lh
#pragma unroll
            for (int mt = 0; mt < 4; mt++)
#pragma unroll
                for (int nt = 0; nt < 4; nt++)
                    mma16816(acc[mt * 4 + nt], al[mt], bh[nt]);
        }
        bi    = (bi    == 2) ? 0 : bi + 1;
        bnext = (bnext == 2) ? 0 : bnext + 1;
    }
    __syncthreads();   // callers reuse smem right after
#undef PREFETCH
}

// ---------------------------------------------------------------------------
// Fused Q/K/V projection + RoPE/scale/split (Q,K) or transpose/split (V).
// grid (16, 96): x = bm (fast, L2-friendly), y = weight*32 + n-tile.
// ---------------------------------------------------------------------------
__global__ __launch_bounds__(256, 2) void gemm_qkv()
{
    extern __shared__ __align__(16) char smraw[];
    const int which = blockIdx.y >> 5;            // 0=Q,1=K,2=V
    const int bn    = (blockIdx.y & 31) * 128;
    const int bm    = blockIdx.x * 128;

    float acc[16][4];
    gemm_mainloop(d_xh, d_xl, d_wh[which], d_wl[which], bm, bn, s2u(smraw), acc);

    // stage acc tile -> smem fp32 [128][130]
    float* smf = (float*)smraw;
    const int lane = threadIdx.x & 31;
    const int warp = threadIdx.x >> 5;
    const int wm = warp & 1, wn = warp >> 1;
#pragma unroll
    for (int mt = 0; mt < 4; mt++)
#pragma unroll
        for (int nt = 0; nt < 4; nt++) {
            int r = wm * 64 + mt * 16 + (lane >> 2);
            int c = wn * 32 + nt * 8 + 2 * (lane & 3);
            float2 v0 = { acc[mt * 4 + nt][0], acc[mt * 4 + nt][1] };
            float2 v1 = { acc[mt * 4 + nt][2], acc[mt * 4 + nt][3] };
            *(float2*)&smf[r * 130 + c]       = v0;
            *(float2*)&smf[(r + 8) * 130 + c] = v1;
        }
    __syncthreads();

    if (which == 2) {
        // V: transposed split write  d_vt*[bn+c][bm+s]
#pragma unroll 8
        for (int i = 0; i < 64; i++) {
            int idx = i * 256 + threadIdx.x;
            int c = idx >> 7, s = idx & 127;
            float v = smf[s * 130 + c];
            __nv_bfloat16 hi = __float2bfloat16(v);
            size_t o = (size_t)(bn + c) * S_LEN + bm + s;
            d_vth[o] = hi;
            d_vtl[o] = __float2bfloat16(v - __bfloat162float(hi));
        }
    } else {
        // Q/K: RoPE (+scale for Q) + split
        __nv_bfloat16* oh = which ? d_kh2 : d_qh;
        __nv_bfloat16* ol = which ? d_kl2 : d_ql;
        const float sc = which ? 1.0f : 0.08838834764831845f;
        const float LOG2_10000 = 13.287712379549449f;
#pragma unroll 8
        for (int p = 0; p < 32; p++) {
            int pid = p * 256 + threadIdx.x;
            int row = pid >> 6, d = pid & 63;
            int sg = bm + row;
            float ex   = (float)(2 * d) * (1.0f / 128.0f);
            float invf = exp2f(-ex * LOG2_10000);
            float ang  = (float)sg * invf;
            float cv = cosf(ang), sv = sinf(ang);
            float a = smf[row * 130 + d], b = smf[row * 130 + d + 64];
            float ra = (a * cv - b * sv) * sc;
            float rb = (b * cv + a * sv) * sc;
            __nv_bfloat16 h1 = __float2bfloat16(ra);
            __nv_bfloat16 h2 = __float2bfloat16(rb);
            size_t o1 = (size_t)sg * DM + bn + d;
            oh[o1]      = h1;
            ol[o1]      = __float2bfloat16(ra - __bfloat162float(h1));
            oh[o1 + 64] = h2;
            ol[o1 + 64] = __float2bfloat16(rb - __bfloat162float(h2));
        }
    }
}

// ---------------------------------------------------------------------------
// Output projection.  grid (16, 32): x = bm (fast).  Plain fp32 epilogue.
// ---------------------------------------------------------------------------
__global__ __launch_bounds__(256, 2) void gemm_wo(float* __restrict__ out)
{
    extern __shared__ __align__(16) char smraw[];
    const int bm = blockIdx.x * 128;
    const int bn = blockIdx.y * 128;

    float acc[16][4];
    gemm_mainloop(d_ah, d_al, d_wh[3], d_wl[3], bm, bn, s2u(smraw), acc);

    const int lane = threadIdx.x & 31;
    const int warp = threadIdx.x >> 5;
    const int wm = warp & 1, wn = warp >> 1;
#pragma unroll
    for (int mt = 0; mt < 4; mt++)
#pragma unroll
        for (int nt = 0; nt < 4; nt++) {
            int row = bm + wm * 64 + mt * 16 + (lane >> 2);
            int col = bn + wn * 32 + nt * 8 + 2 * (lane & 3);
            float2 v0 = { acc[mt * 4 + nt][0], acc[mt * 4 + nt][1] };
            float2 v1 = { acc[mt * 4 + nt][2], acc[mt * 4 + nt][3] };
            *(float2*)(out + (size_t)row * DM + col)       = v0;
            *(float2*)(out + (size_t)(row + 8) * DM + col) = v1;
        }
}

// ---------------------------------------------------------------------------
// Flash attention.  MMA issue reordered into passes (same per-acc order).
// ---------------------------------------------------------------------------
#define ATTN_SMEM (65536 + 2 * 65536)   // 192 KB

__global__ __launch_bounds__(256, 1) void attn_mma()
{
    extern __shared__ __align__(16) char araw[];
    const uint32_t sb  = s2u(araw);
    const uint32_t sQh = sb, sQl = sb + 32768;

    const int qtb = (int)(gridDim.x - 1) - (int)blockIdx.x;
    const int h   = blockIdx.y;
    const int q0  = qtb * 128;
    const int tid = threadIdx.x;
    const int lane = tid & 31;
    const int warp = tid >> 5;
    const int R   = warp * 16;

#pragma unroll
    for (int t = 0; t < 8; t++) {
        int cid = tid + t * 256;
        int r = cid >> 4, c = cid & 15;
        size_t g = (size_t)(q0 + r) * DM + h * HD + c * 8;
        uint32_t so = r * 256 + swz16(r, c) * 16;
        CPA16(sQh + so, d_qh + g);
        CPA16(sQl + so, d_ql + g);
    }

#define PRE_KV(k0_, bi_)                                                        \
    do {                                                                        \
        const uint32_t bb_ = sb + 65536 + (bi_) * 65536;                        \
        _Pragma("unroll")                                                       \
        for (int t_ = 0; t_ < 4; t_++) {                                        \
            int cid_ = tid + t_ * 256;                                          \
            int kr_ = cid_ >> 4, kc_ = cid_ & 15;                               \
            size_t gk_ = (size_t)((k0_) + kr_) * DM + h * HD + kc_ * 8;         \
            uint32_t ko_ = kr_ * 256 + swz16(kr_, kc_) * 16;                    \
            CPA16(bb_ + ko_,         d_kh2 + gk_);                              \
            CPA16(bb_ + 16384 + ko_, d_kl2 + gk_);                              \
            int vr_ = cid_ >> 3, vc_ = cid_ & 7;                                \
            size_t gv_ = (size_t)(h * HD + vr_) * S_LEN + (k0_) + vc_ * 8;      \
            uint32_t vo_ = vr_ * 128 + swz8(vr_, vc_) * 16;                     \
            CPA16(bb_ + 32768 + vo_, d_vth + gv_);                              \
            CPA16(bb_ + 49152 + vo_, d_vtl + gv_);                              \
        }                                                                       \
    } while (0)

    int kb_lo = 2 * qtb - 16; if (kb_lo < 0) kb_lo = 0;
    const int niter = 2 * qtb + 1 - kb_lo + 1;

    PRE_KV(kb_lo * 64, 0);
    CPC();

    float m0 = -1e30f, m1 = -1e30f, l0 = 0.0f, l1 = 0.0f;
    float o[16][4];
#pragma unroll
    for (int p = 0; p < 16; p++)
#pragma unroll
        for (int j = 0; j < 4; j++) o[p][j] = 0.0f;

    const int r0  = lane >> 2;
    const int cb  = 2 * (lane & 3);
    const int gi0 = q0 + R + r0;
    const int gi1 = gi0 + 8;

    for (int it = 0; it < niter; it++) {
        const int k0 = (kb_lo + it) * 64;
        const int bi = it & 1;
        if (it + 1 < niter) {
            PRE_KV(k0 + 64, (it + 1) & 1);
            CPC();
            CPW1();
        } else {
            CPW0();
        }
        __syncthreads();

        const uint32_t bKh = sb + 65536 + bi * 65536;
        const uint32_t bKl = bKh + 16384;
        const uint32_t bVh = bKh + 32768;
        const uint32_t bVl = bKh + 49152;

        // ---- S = Q K^T (reordered: 3 passes over 8 independent accs)
        float s[8][4];
#pragma unroll
        for (int j = 0; j < 8; j++)
#pragma unroll
            for (int e = 0; e < 4; e++) s[j][e] = 0.0f;

#pragma unroll
        for (int ks = 0; ks < 8; ks++) {
            const int qrow = R + (lane & 15);
            const int qc   = 2 * ks + (lane >> 4);
            uint32_t qoff  = qrow * 256 + swz16(qrow, qc) * 16;
            uint32_t qh4[4], ql4[4];
            LDSM4(qh4[0], qh4[1], qh4[2], qh4[3], sQh + qoff);
            LDSM4(ql4[0], ql4[1], ql4[2], ql4[3], sQl + qoff);
            const int bck = 2 * ks + ((lane >> 3) & 1);
            uint32_t kh[4][4], kl[4][4];
#pragma unroll
            for (int p = 0; p < 4; p++) {
                const int krow = p * 16 + (lane & 7) + ((lane >> 4) << 3);
                uint32_t koff = krow * 256 + swz16(krow, bck) * 16;
                LDSM4(kh[p][0], kh[p][1], kh[p][2], kh[p][3], bKh + koff);
                LDSM4(kl[p][0], kl[p][1], kl[p][2], kl[p][3], bKl + koff);
            }
            // pass 1: qh·kh
#pragma unroll
            for (int p = 0; p < 4; p++) {
                mma16816(s[2 * p],     qh4, kh[p] + 0);
                mma16816(s[2 * p + 1], qh4, kh[p] + 2);
            }
            // pass 2: qh·kl
#pragma unroll
            for (int p = 0; p < 4; p++) {
                mma16816(s[2 * p],     qh4, kl[p] + 0);
                mma16816(s[2 * p + 1], qh4, kl[p] + 2);
            }
            // pass 3: ql·kh
#pragma unroll
            for (int p = 0; p < 4; p++) {
                mma16816(s[2 * p],     ql4, kh[p] + 0);
                mma16816(s[2 * p + 1], ql4, kh[p] + 2);
            }
        }

        // ---- mask (skip interior tiles)
        const bool need_mask = !((k0 + 63 <= q0 + R) && (k0 >= q0 + R - 1008));
        if (need_mask) {
#pragma unroll
            for (int j = 0; j < 8; j++) {
                int gj0 = k0 + j * 8 + cb, gj1 = gj0 + 1;
                if (gj0 > gi0 || gj0 + WIN <= gi0) s[j][0] = -1e30f;
                if (gj1 > gi0 || gj1 + WIN <= gi0) s[j][1] = -1e30f;
                if (gj0 > gi1 || gj0 + WIN <= gi1) s[j][2] = -1e30f;
                if (gj1 > gi1 || gj1 + WIN <= gi1) s[j][3] = -1e30f;
            }
        }

        // ---- online softmax
        float t0 = -1e30f, t1 = -1e30f;
#pragma unroll
        for (int j = 0; j < 8; j++) {
            t0 = fmaxf(t0, fmaxf(s[j][0], s[j][1]));
            t1 = fmaxf(t1, fmaxf(s[j][2], s[j][3]));
        }
        t0 = fmaxf(t0, __shfl_xor_sync(0xffffffffu, t0, 1));
        t0 = fmaxf(t0, __shfl_xor_sync(0xffffffffu, t0, 2));
        t1 = fmaxf(t1, __shfl_xor_sync(0xffffffffu, t1, 1));
        t1 = fmaxf(t1, __shfl_xor_sync(0xffffffffu, t1, 2));
        float mn0 = fmaxf(m0, t0), mn1 = fmaxf(m1, t1);
        float c0 = __expf(m0 - mn0), c1 = __expf(m1 - mn1);
        m0 = mn0; m1 = mn1;
        float rs0 = 0.0f, rs1 = 0.0f;
#pragma unroll
        for (int j = 0; j < 8; j++) {
            s[j][0] = __expf(s[j][0] - mn0); rs0 += s[j][0];
            s[j][1] = __expf(s[j][1] - mn0); rs0 += s[j][1];
            s[j][2] = __expf(s[j][2] - mn1); rs1 += s[j][2];
            s[j][3] = __expf(s[j][3] - mn1); rs1 += s[j][3];
        }
        rs0 += __shfl_xor_sync(0xffffffffu, rs0, 1);
        rs0 += __shfl_xor_sync(0xffffffffu, rs0, 2);
        rs1 += __shfl_xor_sync(0xffffffffu, rs1, 1);
        rs1 += __shfl_xor_sync(0xffffffffu, rs1, 2);
        l0 = l0 * c0 + rs0;
        l1 = l1 * c1 + rs1;
#pragma unroll
        for (int p = 0; p < 16; p++) {
            o[p][0] *= c0; o[p][1] *= c0;
            o[p][2] *= c1; o[p][3] *= c1;
        }

        // ---- P -> A fragments, hi/lo split
        uint32_t pah[4][4], pal[4][4];
#pragma unroll
        for (int ks2 = 0; ks2 < 4; ks2++) {
            int j = 2 * ks2;
            split2(s[j][0],     s[j][1],     pah[ks2][0], pal[ks2][0]);
            split2(s[j][2],     s[j][3],     pah[ks2][1], pal[ks2][1]);
            split2(s[j + 1][0], s[j + 1][1], pah[ks2][2], pal[ks2][2]);
            split2(s[j + 1][2], s[j + 1][3], pah[ks2][3], pal[ks2][3]);
        }

        // ---- O += P V (reordered: 3 passes over 8 independent o-pairs)
#pragma unroll
        for (int ks2 = 0; ks2 < 4; ks2++) {
            const int vck = 2 * ks2 + ((lane >> 3) & 1);
#pragma unroll
            for (int g = 0; g < 2; g++) {
                uint32_t vh[4][4], vl[4][4];
#pragma unroll
                for (int pp = 0; pp < 4; pp++) {
                    const int vrow = (g * 4 + pp) * 16 + (lane & 7) + ((lane >> 4) << 3);
                    uint32_t voff = vrow * 128 + swz8(vrow, vck) * 16;
                    LDSM4(vh[pp][0], vh[pp][1], vh[pp][2], vh[pp][3], bVh + voff);
                    LDSM4(vl[pp][0], vl[pp][1], vl[pp][2], vl[pp][3], bVl + voff);
                }
                // pass 1: pah·vh
#pragma unroll
                for (int pp = 0; pp < 4; pp++) {
                    const int p = g * 4 + pp;
                    mma16816(o[2 * p],     pah[ks2], vh[pp] + 0);
                    mma16816(o[2 * p + 1], pah[ks2], vh[pp] + 2);
                }
                // pass 2: pah·vl
#pragma unroll
                for (int pp = 0; pp < 4; pp++) {
                    const int p = g * 4 + pp;
                    mma16816(o[2 * p],     pah[ks2], vl[pp] + 0);
                    mma16816(o[2 * p + 1], pah[ks2], vl[pp] + 2);
                }
                // pass 3: pal·vh
#pragma unroll
                for (int pp = 0; pp < 4; pp++) {
                    const int p = g * 4 + pp;
                    mma16816(o[2 * p],     pal[ks2], vh[pp] + 0);
                    mma16816(o[2 * p + 1], pal[ks2], vh[pp] + 2);
                }
            }
        }
        __syncthreads();
    }

    // ---- epilogue: normalize + fused hi/lo split (feeds gemm_wo directly)
    const float inv0 = 1.0f / l0;
    const float inv1 = 1.0f / l1;
#pragma unroll
    for (int p = 0; p < 16; p++) {
        int col = h * HD + p * 8 + cb;
        uint32_t hi, lo;
        split2(o[p][0] * inv0, o[p][1] * inv0, hi, lo);
        *(uint32_t*)(d_ah + (size_t)gi0 * DM + col) = hi;
        *(uint32_t*)(d_al + (size_t)gi0 * DM + col) = lo;
        split2(o[p][2] * inv1, o[p][3] * inv1, hi, lo);
        *(uint32_t*)(d_ah + (size_t)gi1 * DM + col) = hi;
        *(uint32_t*)(d_al + (size_t)gi1 * DM + col) = lo;
    }
#undef PRE_KV
}

// ---------------------------------------------------------------------------
extern "C" void kernel_launch(void* const* d_in, const int* in_sizes, int n_in,
                              void* d_out, int out_size)
{
    (void)in_sizes; (void)n_in; (void)out_size;
    const float* x  = (const float*)d_in[0];
    const float* Wq = (const float*)d_in[1];
    const float* Wk = (const float*)d_in[2];
    const float* Wv = (const float*)d_in[3];
    const float* Wo = (const float*)d_in[4];
    float* out = (float*)d_out;

    cudaFuncSetAttribute(gemm_qkv, cudaFuncAttributeMaxDynamicSharedMemorySize, GEMM_SMEM);
    cudaFuncSetAttribute(gemm_wo,  cudaFuncAttributeMaxDynamicSharedMemorySize, GEMM_SMEM);
    cudaFuncSetAttribute(attn_mma, cudaFuncAttributeMaxDynamicSharedMemorySize, ATTN_SMEM);

    const int XB = (S_LEN * DM) / 1024;   // 8192
    const int WB = (DM * DM) / 1024;      // 16384

    split_x_kernel<<<XB, 256>>>(x);                       // launch 0
    split_w_kernel<<<4 * WB, 256>>>(Wq, Wk, Wv, Wo);      // launch 1

    gemm_qkv<<<dim3(16, 96), 256, GEMM_SMEM>>>();         // launch 2

    attn_mma<<<dim3(S_LEN / 128, NH), 256, ATTN_SMEM>>>();// launch 3 (profiled)

    gemm_wo<<<dim3(16, 32), 256, GEMM_SMEM>>>(out);       // launch 4
}